// round 15
// baseline (speedup 1.0000x reference)
#include <cuda_runtime.h>
#include <cuda_fp16.h>
#include <mma.h>
#include <math.h>

using namespace nvcuda;
typedef __half hf;

// ---------------- problem constants ----------------
#define NN 50000
#define NPAD 50048            // 391 * 128
#define EE 600000
#define HID 128
#define NEG_SLOPE 0.2f
#define LN_EPS 1e-5f

// GEMM: BM=128, BN=128, BK=64, 2-stage cp.async, warp tile 32x64
#define LDA_SM 72
#define LDB_SM 136
#define A_ST (128 * LDA_SM)
#define B_ST (64 * LDB_SM)
#define SM_GEMM ((2 * A_ST + 2 * B_ST) * 2 + 16 * 128 * 4)   // 79872

// prep-splits kernel block partition (hist moved to side stream)
#define PREP_SPH_B  ((NPAD * 32 + 255) / 256)
#define PREP_SPW_B  ((24576 + (NPAD - NN) * 32 + 255) / 256)
#define PREP_TOTAL_B (PREP_SPH_B + PREP_SPW_B)

// ---------------- scratch ----------------
__device__ float g_h1[NPAD * HID];
// CSR scratch
__device__ int g_ecnt[NN];
__device__ int g_eoff[NN];
__device__ int g_cursor[NN];
__device__ int g_bsum[128];
__device__ int g_esrc[EE];
// fp16 tensors
__device__ hf g_fs[NPAD * HID];
__device__ hf g_fd[NPAD * HID];
__device__ hf g_h_f16[NPAD * HID];
__device__ hf g_h1_f16[NPAD * HID];
__device__ hf g_t_f16[NPAD * 2 * HID];
__device__ hf g_Ws[HID * HID];
__device__ hf g_Wd[HID * HID];
__device__ hf g_W1[HID * 2 * HID];
__device__ hf g_W2[2 * HID * HID];

// ---------------- cp.async helpers ----------------
__device__ __forceinline__ void cp16(void* smem, const void* gmem) {
    unsigned saddr = (unsigned)__cvta_generic_to_shared(smem);
    asm volatile("cp.async.cg.shared.global [%0], [%1], 16;" :: "r"(saddr), "l"(gmem));
}
__device__ __forceinline__ void cp_commit() {
    asm volatile("cp.async.commit_group;" ::: "memory");
}
template <int N>
__device__ __forceinline__ void cp_wait() {
    asm volatile("cp.async.wait_group %0;" :: "n"(N) : "memory");
}

// ---------------- conversion helpers ----------------
__device__ __forceinline__ uint2 f4_to_h4(float4 v) {
    __half2 p0 = __floats2half2_rn(v.x, v.y);
    __half2 p1 = __floats2half2_rn(v.z, v.w);
    uint2 u;
    u.x = *reinterpret_cast<unsigned*>(&p0);
    u.y = *reinterpret_cast<unsigned*>(&p1);
    return u;
}
__device__ __forceinline__ float4 h4_to_f4(uint2 u) {
    __half2 p0 = *reinterpret_cast<__half2*>(&u.x);
    __half2 p1 = *reinterpret_cast<__half2*>(&u.y);
    float2 a = __half22float2(p0);
    float2 b = __half22float2(p1);
    return make_float4(a.x, a.y, b.x, b.y);
}

// ---------------- prep: h->fp16 + weights->fp16 (hist moved off-path) ----------
__global__ void prep_splits(
    const float* __restrict__ h, hf* __restrict__ h_f16,
    const float* __restrict__ Ws, const float* __restrict__ Wd,
    const float* __restrict__ W1, const float* __restrict__ W2,
    hf* __restrict__ Wsh, hf* __restrict__ Wdh,
    hf* __restrict__ W1h, hf* __restrict__ W2h,
    hf* __restrict__ h1_f16)
{
    int b = blockIdx.x;
    if (b < PREP_SPH_B) {
        int i = b * 256 + threadIdx.x;
        if (i >= NPAD * 32) return;
        int row = i >> 5;
        float4 v = make_float4(0.f, 0.f, 0.f, 0.f);
        if (row < NN) v = reinterpret_cast<const float4*>(h)[i];
        reinterpret_cast<uint2*>(h_f16)[i] = f4_to_h4(v);
        return;
    }
    b -= PREP_SPH_B;
    {
        int i = b * 256 + threadIdx.x;
        if (i >= 24576 + (NPAD - NN) * 32) return;
        if (i >= 24576) {
            int j = i - 24576;
            reinterpret_cast<uint2*>(h1_f16 + (size_t)NN * HID)[j] = make_uint2(0u, 0u);
            return;
        }
        const float* s; hf* p; int j = i;
        if (j < 4096)        { s = Ws; p = Wsh; }
        else if (j < 8192)   { j -= 4096;  s = Wd; p = Wdh; }
        else if (j < 16384)  { j -= 8192;  s = W1; p = W1h; }
        else                 { j -= 16384; s = W2; p = W2h; }
        float4 v = reinterpret_cast<const float4*>(s)[j];
        reinterpret_cast<uint2*>(p)[j] = f4_to_h4(v);
    }
}

// ---------------- CSR build (entire chain runs on side stream) ----------------
__global__ void hist_kernel(const int* __restrict__ dst, int* __restrict__ cnt) {
    int e = blockIdx.x * blockDim.x + threadIdx.x;
    if (e < EE) atomicAdd(&cnt[dst[e]], 1);
}

__global__ void scan1(const int* __restrict__ cnt, int* __restrict__ excl,
                      int* __restrict__ bsum) {
    __shared__ int sh[512];
    int i = blockIdx.x * 512 + threadIdx.x;
    int v = (i < NN) ? cnt[i] : 0;
    sh[threadIdx.x] = v;
    __syncthreads();
    #pragma unroll
    for (int off = 1; off < 512; off <<= 1) {
        int t = (threadIdx.x >= off) ? sh[threadIdx.x - off] : 0;
        __syncthreads();
        sh[threadIdx.x] += t;
        __syncthreads();
    }
    if (i < NN) excl[i] = sh[threadIdx.x] - v;
    if (threadIdx.x == 511) bsum[blockIdx.x] = sh[511];
}

__global__ void scan2(int* __restrict__ bsum, int nb) {
    __shared__ int sh[128];
    int v = (threadIdx.x < nb) ? bsum[threadIdx.x] : 0;
    sh[threadIdx.x] = v;
    __syncthreads();
    #pragma unroll
    for (int off = 1; off < 128; off <<= 1) {
        int t = (threadIdx.x >= off) ? sh[threadIdx.x - off] : 0;
        __syncthreads();
        sh[threadIdx.x] += t;
        __syncthreads();
    }
    if (threadIdx.x < nb) bsum[threadIdx.x] = sh[threadIdx.x] - v;
}

__global__ void scan3(int* __restrict__ excl, const int* __restrict__ bsum,
                      int* __restrict__ cursor) {
    int i = blockIdx.x * 512 + threadIdx.x;
    if (i < NN) {
        int v = excl[i] + bsum[blockIdx.x];
        excl[i] = v;
        cursor[i] = v;
    }
}

__global__ void scatter_kernel(const int* __restrict__ src, const int* __restrict__ dst,
                               int* __restrict__ cursor, int* __restrict__ esrc) {
    int e = blockIdx.x * blockDim.x + threadIdx.x;
    if (e >= EE) return;
    int pos = atomicAdd(&cursor[dst[e]], 1);
    esrc[pos] = src[e];
}

// ---------------- WMMA pure-fp16 GEMM core: 128x128 tile, BK=64 ----------------
// EPI: 1 = direct half-fragment store (+optional gelu), 2 = fused resid+LN.
template <int KTOT, bool GELU, int EPI>
__device__ __forceinline__ void gemm_core(
    const hf* __restrict__ A_g, int lda,
    const hf* __restrict__ B_g, int ldb,
    const float* __restrict__ bias,
    hf* __restrict__ Cf16,
    int ldc, int ccol0, int m0,
    const float* __restrict__ resid, const float* __restrict__ lng,
    const float* __restrict__ lnb, float* __restrict__ outp)
{
    extern __shared__ hf sm[];
    hf* AS[2] = { sm,            sm + A_ST };
    hf* BS[2] = { sm + 2 * A_ST, sm + 2 * A_ST + B_ST };
    float* bias_sm = (float*)(sm + 2 * A_ST + 2 * B_ST);   // [16][128]

    const int tid = threadIdx.x;
    const int wid = tid >> 5;
    const int wm = wid & 3;
    const int wn = wid >> 2;

    constexpr int KC = KTOT / 64;

    auto load_stage = [&](int kc, int st) {
        #pragma unroll
        for (int i = tid; i < 1024; i += 256) {
            int r = i >> 3, c8 = (i & 7) * 8;
            size_t go = (size_t)(m0 + r) * lda + kc * 64 + c8;
            cp16(AS[st] + r * LDA_SM + c8, A_g + go);
        }
        #pragma unroll
        for (int i = tid; i < 1024; i += 256) {
            int r = i >> 4, c8 = (i & 15) * 8;
            size_t go = (size_t)(kc * 64 + r) * ldb + ccol0 + c8;
            cp16(BS[st] + r * LDB_SM + c8, B_g + go);
        }
        cp_commit();
    };

    load_stage(0, 0);

    for (int i = tid; i < 16 * 128; i += 256)
        bias_sm[i] = bias[ccol0 + (i & 127)];
    __syncthreads();

    wmma::fragment<wmma::accumulator, 16, 16, 16, float> acc[2][4];
    #pragma unroll
    for (int mi = 0; mi < 2; mi++)
        #pragma unroll
        for (int nj = 0; nj < 4; nj++)
            wmma::load_matrix_sync(acc[mi][nj], bias_sm + wn * 64 + nj * 16, 128, wmma::mem_row_major);

    #pragma unroll
    for (int kc = 0; kc < KC; kc++) {
        if (kc + 1 < KC) load_stage(kc + 1, (kc + 1) & 1);
        if (kc + 1 < KC) cp_wait<1>(); else cp_wait<0>();
        __syncthreads();

        const int st = kc & 1;
        #pragma unroll
        for (int kk = 0; kk < 4; kk++) {
            wmma::fragment<wmma::matrix_a, 16, 16, 16, hf, wmma::row_major> a[2];
            wmma::fragment<wmma::matrix_b, 16, 16, 16, hf, wmma::row_major> bfr[4];
            #pragma unroll
            for (int mi = 0; mi < 2; mi++)
                wmma::load_matrix_sync(a[mi], AS[st] + (wm * 32 + mi * 16) * LDA_SM + kk * 16, LDA_SM);
            #pragma unroll
            for (int nj = 0; nj < 4; nj++)
                wmma::load_matrix_sync(bfr[nj], BS[st] + (kk * 16) * LDB_SM + wn * 64 + nj * 16, LDB_SM);
            #pragma unroll
            for (int mi = 0; mi < 2; mi++)
                #pragma unroll
                for (int nj = 0; nj < 4; nj++)
                    wmma::mma_sync(acc[mi][nj], a[mi], bfr[nj], acc[mi][nj]);
        }
        __syncthreads();
    }

    if (GELU) {
        #pragma unroll
        for (int mi = 0; mi < 2; mi++)
            #pragma unroll
            for (int nj = 0; nj < 4; nj++)
                #pragma unroll
                for (int i = 0; i < acc[mi][nj].num_elements; i++) {
                    float x = acc[mi][nj].x[i];
                    acc[mi][nj].x[i] = 0.5f * x * (1.0f + erff(x * 0.70710678118654752f));
                }
    }

    if (EPI == 1) {
        // direct half-fragment store: fp32 and fp16 accumulator fragments share
        // the per-thread element mapping on sm_80+; convert elementwise and store.
        #pragma unroll
        for (int mi = 0; mi < 2; mi++)
            #pragma unroll
            for (int nj = 0; nj < 4; nj++) {
                wmma::fragment<wmma::accumulator, 16, 16, 16, hf> hc;
                #pragma unroll
                for (int i = 0; i < hc.num_elements; i++)
                    hc.x[i] = __float2half_rn(acc[mi][nj].x[i]);
                hf* cp = Cf16 + (size_t)(m0 + wm * 32 + mi * 16) * ldc + ccol0 + wn * 64 + nj * 16;
                wmma::store_matrix_sync(cp, hc, ldc, wmma::mem_row_major);
            }
    } else {
        // EPI==2: fused residual + LayerNorm on complete 128-wide rows
        float* stageF = (float*)sm;   // 128 x 132 fp32 = 67584 <= 71680
        #pragma unroll
        for (int mi = 0; mi < 2; mi++)
            #pragma unroll
            for (int nj = 0; nj < 4; nj++)
                wmma::store_matrix_sync(stageF + (wm * 32 + mi * 16) * 132 + wn * 64 + nj * 16,
                                        acc[mi][nj], 132, wmma::mem_row_major);
        __syncthreads();
        int lane = tid & 31;
        float4 gg = reinterpret_cast<const float4*>(lng)[lane];
        float4 bb = reinterpret_cast<const float4*>(lnb)[lane];
        #pragma unroll
        for (int rr = 0; rr < 16; rr++) {
            int r = wid * 16 + rr;
            int row = m0 + r;
            if (row >= NN) continue;
            float4 v = *reinterpret_cast<const float4*>(stageF + r * 132 + lane * 4);
            float4 rv = reinterpret_cast<const float4*>(resid)[(size_t)row * 32 + lane];
            v.x += rv.x; v.y += rv.y; v.z += rv.z; v.w += rv.w;

            float s1 = v.x + v.y + v.z + v.w;
            float s2 = v.x * v.x + v.y * v.y + v.z * v.z + v.w * v.w;
            #pragma unroll
            for (int off = 16; off > 0; off >>= 1) {
                s1 += __shfl_xor_sync(0xffffffffu, s1, off);
                s2 += __shfl_xor_sync(0xffffffffu, s2, off);
            }
            float mu = s1 * (1.0f / HID);
            float var = s2 * (1.0f / HID) - mu * mu;
            float rstd = rsqrtf(var + LN_EPS);

            float4 o;
            o.x = (v.x - mu) * rstd * gg.x + bb.x;
            o.y = (v.y - mu) * rstd * gg.y + bb.y;
            o.z = (v.z - mu) * rstd * gg.z + bb.z;
            o.w = (v.w - mu) * rstd * gg.w + bb.w;
            reinterpret_cast<float4*>(outp)[(size_t)row * 32 + lane] = o;
        }
    }
}

__global__ __launch_bounds__(256, 2) void gemm_srcdst(
    const hf* __restrict__ h_f16,
    const hf* __restrict__ Ws, const float* __restrict__ bsrc,
    const hf* __restrict__ Wd, const float* __restrict__ bdst,
    hf* __restrict__ fs, hf* __restrict__ fd)
{
    int m0 = blockIdx.x * 128;
    if (blockIdx.y == 0)
        gemm_core<128, false, 1>(h_f16, 128, Ws, 128, bsrc, fs, 128, 0, m0,
                                 nullptr, nullptr, nullptr, nullptr);
    else
        gemm_core<128, false, 1>(h_f16, 128, Wd, 128, bdst, fd, 128, 0, m0,
                                 nullptr, nullptr, nullptr, nullptr);
}

__global__ __launch_bounds__(256, 2) void gemm_ffn1(
    const hf* __restrict__ h1_f16,
    const hf* __restrict__ W1, const float* __restrict__ bf1,
    hf* __restrict__ t_f16)
{
    gemm_core<128, true, 1>(h1_f16, 128, W1, 256, bf1,
                            t_f16, 256, blockIdx.y * 128, blockIdx.x * 128,
                            nullptr, nullptr, nullptr, nullptr);
}

__global__ __launch_bounds__(256, 2) void gemm_ffn2_ln(
    const hf* __restrict__ t_f16,
    const hf* __restrict__ W2, const float* __restrict__ bf2,
    const float* __restrict__ h1, const float* __restrict__ g2,
    const float* __restrict__ be2, float* __restrict__ out)
{
    gemm_core<256, false, 2>(t_f16, 256, W2, 128, bf2,
                             nullptr, 128, 0, blockIdx.x * 128,
                             h1, g2, be2, out);
}

// ---------------- edge logit helper ----------------
__device__ __forceinline__ float edge_logit(float4 vs, float4 vd, float4 va) {
    float x, sum = 0.0f;
    x = vs.x + vd.x; x = (x > 0.f) ? x : NEG_SLOPE * x; sum += x * va.x;
    x = vs.y + vd.y; x = (x > 0.f) ? x : NEG_SLOPE * x; sum += x * va.y;
    x = vs.z + vd.z; x = (x > 0.f) ? x : NEG_SLOPE * x; sum += x * va.z;
    x = vs.w + vd.w; x = (x > 0.f) ? x : NEG_SLOPE * x; sum += x * va.w;
    sum += __shfl_xor_sync(0xffffffffu, sum, 4);
    sum += __shfl_xor_sync(0xffffffffu, sum, 2);
    sum += __shfl_xor_sync(0xffffffffu, sum, 1);
    return sum;
}

// ---------------- fused edge aggregation + LN1 (fp16 gathers, fp32 math) ----
__global__ __launch_bounds__(256) void edge_agg_ln(
    const hf* __restrict__ fs, const hf* __restrict__ fd,
    const int* __restrict__ eoff, const int* __restrict__ ecnt,
    const int* __restrict__ esrc, const float* __restrict__ attn,
    const float* __restrict__ resid,
    const float* __restrict__ g, const float* __restrict__ b,
    float* __restrict__ out, hf* __restrict__ out_f16)
{
    int d = blockIdx.x * 8 + (threadIdx.x >> 5);
    if (d >= NN) return;
    int lane = threadIdx.x & 31;

    const uint2* fsp = reinterpret_cast<const uint2*>(fs);
    float4 va = reinterpret_cast<const float4*>(attn)[lane];
    float4 vd = h4_to_f4(reinterpret_cast<const uint2*>(fd)[(size_t)d * 32 + lane]);

    int i = eoff[d];
    int end = i + ecnt[d];

    float4 acc = make_float4(0.f, 0.f, 0.f, 0.f);
    float den = 0.0f;

    for (; i + 3 < end; i += 4) {
        int s0 = __ldg(esrc + i);
        int s1 = __ldg(esrc + i + 1);
        int s2 = __ldg(esrc + i + 2);
        int s3 = __ldg(esrc + i + 3);
        float4 v0 = h4_to_f4(fsp[(size_t)s0 * 32 + lane]);
        float4 v1 = h4_to_f4(fsp[(size_t)s1 * 32 + lane]);
        float4 v2 = h4_to_f4(fsp[(size_t)s2 * 32 + lane]);
        float4 v3 = h4_to_f4(fsp[(size_t)s3 * 32 + lane]);
        float a0 = __expf(edge_logit(v0, vd, va));
        float a1 = __expf(edge_logit(v1, vd, va));
        float a2 = __expf(edge_logit(v2, vd, va));
        float a3 = __expf(edge_logit(v3, vd, va));
        acc.x += v0.x * a0 + v1.x * a1 + v2.x * a2 + v3.x * a3;
        acc.y += v0.y * a0 + v1.y * a1 + v2.y * a2 + v3.y * a3;
        acc.z += v0.z * a0 + v1.z * a1 + v2.z * a2 + v3.z * a3;
        acc.w += v0.w * a0 + v1.w * a1 + v2.w * a2 + v3.w * a3;
        den += a0 + a1 + a2 + a3;
    }
    for (; i < end; i++) {
        int s = __ldg(esrc + i);
        float4 vs = h4_to_f4(fsp[(size_t)s * 32 + lane]);
        float a = __expf(edge_logit(vs, vd, va));
        acc.x += vs.x * a; acc.y += vs.y * a;
        acc.z += vs.z * a; acc.w += vs.w * a;
        den += a;
    }

    den = (den == 0.0f) ? 1.0f : den;
    float inv = 1.0f / den;
    float4 rv = reinterpret_cast<const float4*>(resid)[(size_t)d * 32 + lane];
    float4 v;
    v.x = acc.x * inv + rv.x; v.y = acc.y * inv + rv.y;
    v.z = acc.z * inv + rv.z; v.w = acc.w * inv + rv.w;

    float s1 = v.x + v.y + v.z + v.w;
    float s2 = v.x * v.x + v.y * v.y + v.z * v.z + v.w * v.w;
    #pragma unroll
    for (int off = 16; off > 0; off >>= 1) {
        s1 += __shfl_xor_sync(0xffffffffu, s1, off);
        s2 += __shfl_xor_sync(0xffffffffu, s2, off);
    }
    float mu = s1 * (1.0f / HID);
    float var = s2 * (1.0f / HID) - mu * mu;
    float rstd = rsqrtf(var + LN_EPS);

    float4 gg = reinterpret_cast<const float4*>(g)[lane];
    float4 bb = reinterpret_cast<const float4*>(b)[lane];
    float4 o;
    o.x = (v.x - mu) * rstd * gg.x + bb.x;
    o.y = (v.y - mu) * rstd * gg.y + bb.y;
    o.z = (v.z - mu) * rstd * gg.z + bb.z;
    o.w = (v.w - mu) * rstd * gg.w + bb.w;
    reinterpret_cast<float4*>(out)[(size_t)d * 32 + lane] = o;
    reinterpret_cast<uint2*>(out_f16)[(size_t)d * 32 + lane] = f4_to_h4(o);
}

// ---------------- launcher ----------------
extern "C" void kernel_launch(void* const* d_in, const int* in_sizes, int n_in,
                              void* d_out, int out_size)
{
    const float* h    = (const float*)d_in[0];
    const int*   src  = (const int*)  d_in[1];
    const int*   dst  = (const int*)  d_in[2];
    const float* Wsrc = (const float*)d_in[3];
    const float* bsrc = (const float*)d_in[4];
    const float* Wdst = (const float*)d_in[5];
    const float* bdst = (const float*)d_in[6];
    const float* attn = (const float*)d_in[7];
    const float* W1   = (const float*)d_in[8];
    const float* bf1  = (const float*)d_in[9];
    const float* W2   = (const float*)d_in[10];
    const float* bf2  = (const float*)d_in[11];
    const float* g1   = (const float*)d_in[12];
    const float* be1  = (const float*)d_in[13];
    const float* g2   = (const float*)d_in[14];
    const float* be2  = (const float*)d_in[15];
    float* out = (float*)d_out;

    float *h1;
    int *ecnt, *eoff, *cursor, *bsum, *esrc;
    hf *fs, *fd, *h_f16, *h1_f16, *t_f16, *Ws, *Wd, *W1h, *W2h;
    cudaGetSymbolAddress((void**)&h1,    g_h1);
    cudaGetSymbolAddress((void**)&ecnt,  g_ecnt);
    cudaGetSymbolAddress((void**)&eoff,  g_eoff);
    cudaGetSymbolAddress((void**)&cursor,g_cursor);
    cudaGetSymbolAddress((void**)&bsum,  g_bsum);
    cudaGetSymbolAddress((void**)&esrc,  g_esrc);
    cudaGetSymbolAddress((void**)&fs,    g_fs);
    cudaGetSymbolAddress((void**)&fd,    g_fd);
    cudaGetSymbolAddress((void**)&h_f16, g_h_f16);
    cudaGetSymbolAddress((void**)&h1_f16,g_h1_f16);
    cudaGetSymbolAddress((void**)&t_f16, g_t_f16);
    cudaGetSymbolAddress((void**)&Ws,    g_Ws);
    cudaGetSymbolAddress((void**)&Wd,    g_Wd);
    cudaGetSymbolAddress((void**)&W1h,   g_W1);
    cudaGetSymbolAddress((void**)&W2h,   g_W2);

    cudaFuncSetAttribute(gemm_srcdst,  cudaFuncAttributeMaxDynamicSharedMemorySize, SM_GEMM);
    cudaFuncSetAttribute(gemm_ffn1,    cudaFuncAttributeMaxDynamicSharedMemorySize, SM_GEMM);
    cudaFuncSetAttribute(gemm_ffn2_ln, cudaFuncAttributeMaxDynamicSharedMemorySize, SM_GEMM);

    static cudaStream_t s_side = nullptr;
    static cudaEvent_t ev_fork = nullptr, ev_join = nullptr;
    if (s_side == nullptr) {
        cudaStreamCreateWithFlags(&s_side, cudaStreamNonBlocking);
        cudaEventCreateWithFlags(&ev_fork, cudaEventDisableTiming);
        cudaEventCreateWithFlags(&ev_join, cudaEventDisableTiming);
    }

    const int GXM = NPAD / 128;   // 391
    const int NB = (NN + 511) / 512;

    // fork immediately: the entire CSR chain depends only on src/dst inputs.
    cudaEventRecord(ev_fork, 0);
    cudaStreamWaitEvent(s_side, ev_fork, 0);
    cudaMemsetAsync(ecnt, 0, NN * sizeof(int), s_side);
    hist_kernel<<<(EE + 255) / 256, 256, 0, s_side>>>(dst, ecnt);
    scan1<<<NB, 512, 0, s_side>>>(ecnt, eoff, bsum);
    scan2<<<1, 128, 0, s_side>>>(bsum, NB);
    scan3<<<NB, 512, 0, s_side>>>(eoff, bsum, cursor);
    scatter_kernel<<<(EE + 255) / 256, 256, 0, s_side>>>(src, dst, cursor, esrc);
    cudaEventRecord(ev_join, s_side);

    // main stream: splits, then srcdst GEMM (concurrent with CSR chain)
    prep_splits<<<PREP_TOTAL_B, 256>>>(h, h_f16, Wsrc, Wdst, W1, W2,
                                       Ws, Wd, W1h, W2h, h1_f16);
    gemm_srcdst<<<dim3(GXM, 2), 256, SM_GEMM>>>(h_f16, Ws, bsrc, Wd, bdst, fs, fd);

    cudaStreamWaitEvent(0, ev_join, 0);

    edge_agg_ln<<<(NN + 7) / 8, 256>>>(fs, fd, eoff, ecnt, esrc, attn,
                                       h, g1, be1, h1, h1_f16);

    gemm_ffn1<<<dim3(GXM, 2), 256, SM_GEMM>>>(h1_f16, W1h, bf1, t_f16);
    gemm_ffn2_ln<<<dim3(GXM, 1), 256, SM_GEMM>>>(t_f16, W2h, bf2, h1, g2, be2, out);
}

// round 16
// speedup vs baseline: 1.0822x; 1.0822x over previous
#include <cuda_runtime.h>
#include <cuda_fp16.h>
#include <mma.h>
#include <math.h>

using namespace nvcuda;
typedef __half hf;

// ---------------- problem constants ----------------
#define NN 50000
#define NPAD 50048            // 391 * 128
#define EE 600000
#define HID 128
#define NEG_SLOPE 0.2f
#define LN_EPS 1e-5f

// GEMM: BM=128, BN=128, BK=64, 2-stage cp.async, warp tile 32x64
#define LDA_SM 72
#define LDB_SM 136
#define A_ST (128 * LDA_SM)
#define B_ST (64 * LDB_SM)
#define SM_GEMM ((2 * A_ST + 2 * B_ST) * 2 + 16 * 128 * 4)   // 79872

// prep kernel block partition (R14 arrangement: hist merged into prep)
#define PREP_HIST_B ((EE + 255) / 256)
#define PREP_SPH_B  ((NPAD * 32 + 255) / 256)
#define PREP_SPW_B  ((24576 + (NPAD - NN) * 32 + 255) / 256)
#define PREP_TOTAL_B (PREP_HIST_B + PREP_SPH_B + PREP_SPW_B)

// ---------------- scratch ----------------
// CSR scratch
__device__ int g_ecnt[NN];
__device__ int g_eoff[NN];
__device__ int g_cursor[NN];
__device__ int g_bsum[128];
__device__ int g_esrc[EE];
// fp16 tensors (h1 exists ONLY in fp16 now)
__device__ hf g_fs[NPAD * HID];
__device__ hf g_fd[NPAD * HID];
__device__ hf g_h_f16[NPAD * HID];
__device__ hf g_h1_f16[NPAD * HID];
__device__ hf g_t_f16[NPAD * 2 * HID];
__device__ hf g_Ws[HID * HID];
__device__ hf g_Wd[HID * HID];
__device__ hf g_W1[HID * 2 * HID];
__device__ hf g_W2[2 * HID * HID];

// ---------------- cp.async helpers ----------------
__device__ __forceinline__ void cp16(void* smem, const void* gmem) {
    unsigned saddr = (unsigned)__cvta_generic_to_shared(smem);
    asm volatile("cp.async.cg.shared.global [%0], [%1], 16;" :: "r"(saddr), "l"(gmem));
}
__device__ __forceinline__ void cp_commit() {
    asm volatile("cp.async.commit_group;" ::: "memory");
}
template <int N>
__device__ __forceinline__ void cp_wait() {
    asm volatile("cp.async.wait_group %0;" :: "n"(N) : "memory");
}

// ---------------- conversion helpers ----------------
__device__ __forceinline__ uint2 f4_to_h4(float4 v) {
    __half2 p0 = __floats2half2_rn(v.x, v.y);
    __half2 p1 = __floats2half2_rn(v.z, v.w);
    uint2 u;
    u.x = *reinterpret_cast<unsigned*>(&p0);
    u.y = *reinterpret_cast<unsigned*>(&p1);
    return u;
}
__device__ __forceinline__ float4 h4_to_f4(uint2 u) {
    __half2 p0 = *reinterpret_cast<__half2*>(&u.x);
    __half2 p1 = *reinterpret_cast<__half2*>(&u.y);
    float2 a = __half22float2(p0);
    float2 b = __half22float2(p1);
    return make_float4(a.x, a.y, b.x, b.y);
}

// ---------------- merged prep: hist + h->fp16 + weights->fp16 (R14 style) ----
__global__ void prep_kernel(
    const int* __restrict__ dst, int* __restrict__ cnt,
    const float* __restrict__ h, hf* __restrict__ h_f16,
    const float* __restrict__ Ws, const float* __restrict__ Wd,
    const float* __restrict__ W1, const float* __restrict__ W2,
    hf* __restrict__ Wsh, hf* __restrict__ Wdh,
    hf* __restrict__ W1h, hf* __restrict__ W2h,
    hf* __restrict__ h1_f16)
{
    int b = blockIdx.x;
    if (b < PREP_HIST_B) {
        int e = b * 256 + threadIdx.x;
        if (e < EE) atomicAdd(&cnt[dst[e]], 1);
        return;
    }
    b -= PREP_HIST_B;
    if (b < PREP_SPH_B) {
        int i = b * 256 + threadIdx.x;
        if (i >= NPAD * 32) return;
        int row = i >> 5;
        float4 v = make_float4(0.f, 0.f, 0.f, 0.f);
        if (row < NN) v = reinterpret_cast<const float4*>(h)[i];
        reinterpret_cast<uint2*>(h_f16)[i] = f4_to_h4(v);
        return;
    }
    b -= PREP_SPH_B;
    {
        int i = b * 256 + threadIdx.x;
        if (i >= 24576 + (NPAD - NN) * 32) return;
        if (i >= 24576) {
            int j = i - 24576;
            reinterpret_cast<uint2*>(h1_f16 + (size_t)NN * HID)[j] = make_uint2(0u, 0u);
            return;
        }
        const float* s; hf* p; int j = i;
        if (j < 4096)        { s = Ws; p = Wsh; }
        else if (j < 8192)   { j -= 4096;  s = Wd; p = Wdh; }
        else if (j < 16384)  { j -= 8192;  s = W1; p = W1h; }
        else                 { j -= 16384; s = W2; p = W2h; }
        float4 v = reinterpret_cast<const float4*>(s)[j];
        reinterpret_cast<uint2*>(p)[j] = f4_to_h4(v);
    }
}

// ---------------- CSR scan/scatter ----------------
__global__ void scan1(const int* __restrict__ cnt, int* __restrict__ excl,
                      int* __restrict__ bsum) {
    __shared__ int sh[512];
    int i = blockIdx.x * 512 + threadIdx.x;
    int v = (i < NN) ? cnt[i] : 0;
    sh[threadIdx.x] = v;
    __syncthreads();
    #pragma unroll
    for (int off = 1; off < 512; off <<= 1) {
        int t = (threadIdx.x >= off) ? sh[threadIdx.x - off] : 0;
        __syncthreads();
        sh[threadIdx.x] += t;
        __syncthreads();
    }
    if (i < NN) excl[i] = sh[threadIdx.x] - v;
    if (threadIdx.x == 511) bsum[blockIdx.x] = sh[511];
}

__global__ void scan2(int* __restrict__ bsum, int nb) {
    __shared__ int sh[128];
    int v = (threadIdx.x < nb) ? bsum[threadIdx.x] : 0;
    sh[threadIdx.x] = v;
    __syncthreads();
    #pragma unroll
    for (int off = 1; off < 128; off <<= 1) {
        int t = (threadIdx.x >= off) ? sh[threadIdx.x - off] : 0;
        __syncthreads();
        sh[threadIdx.x] += t;
        __syncthreads();
    }
    if (threadIdx.x < nb) bsum[threadIdx.x] = sh[threadIdx.x] - v;
}

__global__ void scan3(int* __restrict__ excl, const int* __restrict__ bsum,
                      int* __restrict__ cursor) {
    int i = blockIdx.x * 512 + threadIdx.x;
    if (i < NN) {
        int v = excl[i] + bsum[blockIdx.x];
        excl[i] = v;
        cursor[i] = v;
    }
}

__global__ void scatter_kernel(const int* __restrict__ src, const int* __restrict__ dst,
                               int* __restrict__ cursor, int* __restrict__ esrc) {
    int e = blockIdx.x * blockDim.x + threadIdx.x;
    if (e >= EE) return;
    int pos = atomicAdd(&cursor[dst[e]], 1);
    esrc[pos] = src[e];
}

// ---------------- WMMA pure-fp16 GEMM core: 128x128 tile, BK=64 ----------------
// EPI: 1 = staged fp16 store (+optional gelu), 2 = fused resid(fp16)+LayerNorm.
template <int KTOT, bool GELU, int EPI>
__device__ __forceinline__ void gemm_core(
    const hf* __restrict__ A_g, int lda,
    const hf* __restrict__ B_g, int ldb,
    const float* __restrict__ bias,
    hf* __restrict__ Cf16,
    int ldc, int ccol0, int m0,
    const hf* __restrict__ residh, const float* __restrict__ lng,
    const float* __restrict__ lnb, float* __restrict__ outp)
{
    extern __shared__ hf sm[];
    hf* AS[2] = { sm,            sm + A_ST };
    hf* BS[2] = { sm + 2 * A_ST, sm + 2 * A_ST + B_ST };
    float* bias_sm = (float*)(sm + 2 * A_ST + 2 * B_ST);   // [16][128]

    const int tid = threadIdx.x;
    const int wid = tid >> 5;
    const int wm = wid & 3;
    const int wn = wid >> 2;

    constexpr int KC = KTOT / 64;

    auto load_stage = [&](int kc, int st) {
        #pragma unroll
        for (int i = tid; i < 1024; i += 256) {
            int r = i >> 3, c8 = (i & 7) * 8;
            size_t go = (size_t)(m0 + r) * lda + kc * 64 + c8;
            cp16(AS[st] + r * LDA_SM + c8, A_g + go);
        }
        #pragma unroll
        for (int i = tid; i < 1024; i += 256) {
            int r = i >> 4, c8 = (i & 15) * 8;
            size_t go = (size_t)(kc * 64 + r) * ldb + ccol0 + c8;
            cp16(BS[st] + r * LDB_SM + c8, B_g + go);
        }
        cp_commit();
    };

    load_stage(0, 0);

    for (int i = tid; i < 16 * 128; i += 256)
        bias_sm[i] = bias[ccol0 + (i & 127)];
    __syncthreads();

    wmma::fragment<wmma::accumulator, 16, 16, 16, float> acc[2][4];
    #pragma unroll
    for (int mi = 0; mi < 2; mi++)
        #pragma unroll
        for (int nj = 0; nj < 4; nj++)
            wmma::load_matrix_sync(acc[mi][nj], bias_sm + wn * 64 + nj * 16, 128, wmma::mem_row_major);

    #pragma unroll
    for (int kc = 0; kc < KC; kc++) {
        if (kc + 1 < KC) load_stage(kc + 1, (kc + 1) & 1);
        if (kc + 1 < KC) cp_wait<1>(); else cp_wait<0>();
        __syncthreads();

        const int st = kc & 1;
        #pragma unroll
        for (int kk = 0; kk < 4; kk++) {
            wmma::fragment<wmma::matrix_a, 16, 16, 16, hf, wmma::row_major> a[2];
            wmma::fragment<wmma::matrix_b, 16, 16, 16, hf, wmma::row_major> bfr[4];
            #pragma unroll
            for (int mi = 0; mi < 2; mi++)
                wmma::load_matrix_sync(a[mi], AS[st] + (wm * 32 + mi * 16) * LDA_SM + kk * 16, LDA_SM);
            #pragma unroll
            for (int nj = 0; nj < 4; nj++)
                wmma::load_matrix_sync(bfr[nj], BS[st] + (kk * 16) * LDB_SM + wn * 64 + nj * 16, LDB_SM);
            #pragma unroll
            for (int mi = 0; mi < 2; mi++)
                #pragma unroll
                for (int nj = 0; nj < 4; nj++)
                    wmma::mma_sync(acc[mi][nj], a[mi], bfr[nj], acc[mi][nj]);
        }
        __syncthreads();
    }

    if (GELU) {
        #pragma unroll
        for (int mi = 0; mi < 2; mi++)
            #pragma unroll
            for (int nj = 0; nj < 4; nj++)
                #pragma unroll
                for (int i = 0; i < acc[mi][nj].num_elements; i++) {
                    float x = acc[mi][nj].x[i];
                    acc[mi][nj].x[i] = 0.5f * x * (1.0f + erff(x * 0.70710678118654752f));
                }
    }

    if (EPI == 1) {
        // staged epilogue: coalesced uint2 fp16 stores (R14-proven)
        float* stage = (float*)sm + wid * (32 * 68);
        #pragma unroll
        for (int mi = 0; mi < 2; mi++)
            #pragma unroll
            for (int nj = 0; nj < 4; nj++)
                wmma::store_matrix_sync(stage + mi * 16 * 68 + nj * 16, acc[mi][nj], 68, wmma::mem_row_major);
        __syncwarp();
        int lane = tid & 31;
        #pragma unroll
        for (int it = 0; it < 16; it++) {
            int j = it * 32 + lane;
            int r = j >> 4, c4 = j & 15;
            float4 v = *reinterpret_cast<const float4*>(stage + r * 68 + c4 * 4);
            size_t go = (size_t)(m0 + wm * 32 + r) * ldc + ccol0 + wn * 64 + c4 * 4;
            *reinterpret_cast<uint2*>(Cf16 + go) = f4_to_h4(v);
        }
    } else {
        // EPI==2: fused fp16-residual + LayerNorm on complete 128-wide rows
        float* stageF = (float*)sm;   // 128 x 132 fp32 = 67584 <= 71680
        #pragma unroll
        for (int mi = 0; mi < 2; mi++)
            #pragma unroll
            for (int nj = 0; nj < 4; nj++)
                wmma::store_matrix_sync(stageF + (wm * 32 + mi * 16) * 132 + wn * 64 + nj * 16,
                                        acc[mi][nj], 132, wmma::mem_row_major);
        __syncthreads();
        int lane = tid & 31;
        float4 gg = reinterpret_cast<const float4*>(lng)[lane];
        float4 bb = reinterpret_cast<const float4*>(lnb)[lane];
        #pragma unroll
        for (int rr = 0; rr < 16; rr++) {
            int r = wid * 16 + rr;
            int row = m0 + r;
            if (row >= NN) continue;
            float4 v = *reinterpret_cast<const float4*>(stageF + r * 132 + lane * 4);
            float4 rv = h4_to_f4(reinterpret_cast<const uint2*>(residh)[(size_t)row * 32 + lane]);
            v.x += rv.x; v.y += rv.y; v.z += rv.z; v.w += rv.w;

            float s1 = v.x + v.y + v.z + v.w;
            float s2 = v.x * v.x + v.y * v.y + v.z * v.z + v.w * v.w;
            #pragma unroll
            for (int off = 16; off > 0; off >>= 1) {
                s1 += __shfl_xor_sync(0xffffffffu, s1, off);
                s2 += __shfl_xor_sync(0xffffffffu, s2, off);
            }
            float mu = s1 * (1.0f / HID);
            float var = s2 * (1.0f / HID) - mu * mu;
            float rstd = rsqrtf(var + LN_EPS);

            float4 o;
            o.x = (v.x - mu) * rstd * gg.x + bb.x;
            o.y = (v.y - mu) * rstd * gg.y + bb.y;
            o.z = (v.z - mu) * rstd * gg.z + bb.z;
            o.w = (v.w - mu) * rstd * gg.w + bb.w;
            reinterpret_cast<float4*>(outp)[(size_t)row * 32 + lane] = o;
        }
    }
}

__global__ __launch_bounds__(256, 2) void gemm_srcdst(
    const hf* __restrict__ h_f16,
    const hf* __restrict__ Ws, const float* __restrict__ bsrc,
    const hf* __restrict__ Wd, const float* __restrict__ bdst,
    hf* __restrict__ fs, hf* __restrict__ fd)
{
    int m0 = blockIdx.x * 128;
    if (blockIdx.y == 0)
        gemm_core<128, false, 1>(h_f16, 128, Ws, 128, bsrc, fs, 128, 0, m0,
                                 nullptr, nullptr, nullptr, nullptr);
    else
        gemm_core<128, false, 1>(h_f16, 128, Wd, 128, bdst, fd, 128, 0, m0,
                                 nullptr, nullptr, nullptr, nullptr);
}

__global__ __launch_bounds__(256, 2) void gemm_ffn1(
    const hf* __restrict__ h1_f16,
    const hf* __restrict__ W1, const float* __restrict__ bf1,
    hf* __restrict__ t_f16)
{
    gemm_core<128, true, 1>(h1_f16, 128, W1, 256, bf1,
                            t_f16, 256, blockIdx.y * 128, blockIdx.x * 128,
                            nullptr, nullptr, nullptr, nullptr);
}

__global__ __launch_bounds__(256, 2) void gemm_ffn2_ln(
    const hf* __restrict__ t_f16,
    const hf* __restrict__ W2, const float* __restrict__ bf2,
    const hf* __restrict__ h1_f16, const float* __restrict__ g2,
    const float* __restrict__ be2, float* __restrict__ out)
{
    gemm_core<256, false, 2>(t_f16, 256, W2, 128, bf2,
                             nullptr, 128, 0, blockIdx.x * 128,
                             h1_f16, g2, be2, out);
}

// ---------------- edge logit helper ----------------
__device__ __forceinline__ float edge_logit(float4 vs, float4 vd, float4 va) {
    float x, sum = 0.0f;
    x = vs.x + vd.x; x = (x > 0.f) ? x : NEG_SLOPE * x; sum += x * va.x;
    x = vs.y + vd.y; x = (x > 0.f) ? x : NEG_SLOPE * x; sum += x * va.y;
    x = vs.z + vd.z; x = (x > 0.f) ? x : NEG_SLOPE * x; sum += x * va.z;
    x = vs.w + vd.w; x = (x > 0.f) ? x : NEG_SLOPE * x; sum += x * va.w;
    sum += __shfl_xor_sync(0xffffffffu, sum, 4);
    sum += __shfl_xor_sync(0xffffffffu, sum, 2);
    sum += __shfl_xor_sync(0xffffffffu, sum, 1);
    return sum;
}

// ---------------- fused edge aggregation + LN1 (writes h1 fp16 ONLY) ----------
__global__ __launch_bounds__(256) void edge_agg_ln(
    const hf* __restrict__ fs, const hf* __restrict__ fd,
    const int* __restrict__ eoff, const int* __restrict__ ecnt,
    const int* __restrict__ esrc, const float* __restrict__ attn,
    const float* __restrict__ resid,
    const float* __restrict__ g, const float* __restrict__ b,
    hf* __restrict__ out_f16)
{
    int d = blockIdx.x * 8 + (threadIdx.x >> 5);
    if (d >= NN) return;
    int lane = threadIdx.x & 31;

    const uint2* fsp = reinterpret_cast<const uint2*>(fs);
    float4 va = reinterpret_cast<const float4*>(attn)[lane];
    float4 vd = h4_to_f4(reinterpret_cast<const uint2*>(fd)[(size_t)d * 32 + lane]);

    int i = eoff[d];
    int end = i + ecnt[d];

    float4 acc = make_float4(0.f, 0.f, 0.f, 0.f);
    float den = 0.0f;

    for (; i + 3 < end; i += 4) {
        int s0 = __ldg(esrc + i);
        int s1 = __ldg(esrc + i + 1);
        int s2 = __ldg(esrc + i + 2);
        int s3 = __ldg(esrc + i + 3);
        float4 v0 = h4_to_f4(fsp[(size_t)s0 * 32 + lane]);
        float4 v1 = h4_to_f4(fsp[(size_t)s1 * 32 + lane]);
        float4 v2 = h4_to_f4(fsp[(size_t)s2 * 32 + lane]);
        float4 v3 = h4_to_f4(fsp[(size_t)s3 * 32 + lane]);
        float a0 = __expf(edge_logit(v0, vd, va));
        float a1 = __expf(edge_logit(v1, vd, va));
        float a2 = __expf(edge_logit(v2, vd, va));
        float a3 = __expf(edge_logit(v3, vd, va));
        acc.x += v0.x * a0 + v1.x * a1 + v2.x * a2 + v3.x * a3;
        acc.y += v0.y * a0 + v1.y * a1 + v2.y * a2 + v3.y * a3;
        acc.z += v0.z * a0 + v1.z * a1 + v2.z * a2 + v3.z * a3;
        acc.w += v0.w * a0 + v1.w * a1 + v2.w * a2 + v3.w * a3;
        den += a0 + a1 + a2 + a3;
    }
    for (; i < end; i++) {
        int s = __ldg(esrc + i);
        float4 vs = h4_to_f4(fsp[(size_t)s * 32 + lane]);
        float a = __expf(edge_logit(vs, vd, va));
        acc.x += vs.x * a; acc.y += vs.y * a;
        acc.z += vs.z * a; acc.w += vs.w * a;
        den += a;
    }

    den = (den == 0.0f) ? 1.0f : den;
    float inv = 1.0f / den;
    float4 rv = reinterpret_cast<const float4*>(resid)[(size_t)d * 32 + lane];
    float4 v;
    v.x = acc.x * inv + rv.x; v.y = acc.y * inv + rv.y;
    v.z = acc.z * inv + rv.z; v.w = acc.w * inv + rv.w;

    float s1 = v.x + v.y + v.z + v.w;
    float s2 = v.x * v.x + v.y * v.y + v.z * v.z + v.w * v.w;
    #pragma unroll
    for (int off = 16; off > 0; off >>= 1) {
        s1 += __shfl_xor_sync(0xffffffffu, s1, off);
        s2 += __shfl_xor_sync(0xffffffffu, s2, off);
    }
    float mu = s1 * (1.0f / HID);
    float var = s2 * (1.0f / HID) - mu * mu;
    float rstd = rsqrtf(var + LN_EPS);

    float4 gg = reinterpret_cast<const float4*>(g)[lane];
    float4 bb = reinterpret_cast<const float4*>(b)[lane];
    float4 o;
    o.x = (v.x - mu) * rstd * gg.x + bb.x;
    o.y = (v.y - mu) * rstd * gg.y + bb.y;
    o.z = (v.z - mu) * rstd * gg.z + bb.z;
    o.w = (v.w - mu) * rstd * gg.w + bb.w;
    reinterpret_cast<uint2*>(out_f16)[(size_t)d * 32 + lane] = f4_to_h4(o);
}

// ---------------- launcher (R14 arrangement) ----------------
extern "C" void kernel_launch(void* const* d_in, const int* in_sizes, int n_in,
                              void* d_out, int out_size)
{
    const float* h    = (const float*)d_in[0];
    const int*   src  = (const int*)  d_in[1];
    const int*   dst  = (const int*)  d_in[2];
    const float* Wsrc = (const float*)d_in[3];
    const float* bsrc = (const float*)d_in[4];
    const float* Wdst = (const float*)d_in[5];
    const float* bdst = (const float*)d_in[6];
    const float* attn = (const float*)d_in[7];
    const float* W1   = (const float*)d_in[8];
    const float* bf1  = (const float*)d_in[9];
    const float* W2   = (const float*)d_in[10];
    const float* bf2  = (const float*)d_in[11];
    const float* g1   = (const float*)d_in[12];
    const float* be1  = (const float*)d_in[13];
    const float* g2   = (const float*)d_in[14];
    const float* be2  = (const float*)d_in[15];
    float* out = (float*)d_out;

    int *ecnt, *eoff, *cursor, *bsum, *esrc;
    hf *fs, *fd, *h_f16, *h1_f16, *t_f16, *Ws, *Wd, *W1h, *W2h;
    cudaGetSymbolAddress((void**)&ecnt,  g_ecnt);
    cudaGetSymbolAddress((void**)&eoff,  g_eoff);
    cudaGetSymbolAddress((void**)&cursor,g_cursor);
    cudaGetSymbolAddress((void**)&bsum,  g_bsum);
    cudaGetSymbolAddress((void**)&esrc,  g_esrc);
    cudaGetSymbolAddress((void**)&fs,    g_fs);
    cudaGetSymbolAddress((void**)&fd,    g_fd);
    cudaGetSymbolAddress((void**)&h_f16, g_h_f16);
    cudaGetSymbolAddress((void**)&h1_f16,g_h1_f16);
    cudaGetSymbolAddress((void**)&t_f16, g_t_f16);
    cudaGetSymbolAddress((void**)&Ws,    g_Ws);
    cudaGetSymbolAddress((void**)&Wd,    g_Wd);
    cudaGetSymbolAddress((void**)&W1h,   g_W1);
    cudaGetSymbolAddress((void**)&W2h,   g_W2);

    cudaFuncSetAttribute(gemm_srcdst,  cudaFuncAttributeMaxDynamicSharedMemorySize, SM_GEMM);
    cudaFuncSetAttribute(gemm_ffn1,    cudaFuncAttributeMaxDynamicSharedMemorySize, SM_GEMM);
    cudaFuncSetAttribute(gemm_ffn2_ln, cudaFuncAttributeMaxDynamicSharedMemorySize, SM_GEMM);

    static cudaStream_t s_side = nullptr;
    static cudaEvent_t ev_fork = nullptr, ev_join = nullptr;
    if (s_side == nullptr) {
        cudaStreamCreateWithFlags(&s_side, cudaStreamNonBlocking);
        cudaEventCreateWithFlags(&ev_fork, cudaEventDisableTiming);
        cudaEventCreateWithFlags(&ev_join, cudaEventDisableTiming);
    }

    const int GXM = NPAD / 128;   // 391
    const int NB = (NN + 511) / 512;

    // main stream: memset + merged prep (hist/splits) — R14-proven arrangement
    cudaMemsetAsync(ecnt, 0, NN * sizeof(int));
    prep_kernel<<<PREP_TOTAL_B, 256>>>(dst, ecnt, h, h_f16,
                                       Wsrc, Wdst, W1, W2,
                                       Ws, Wd, W1h, W2h, h1_f16);

    // fork: CSR scan/scatter on side stream, concurrent with gemm_srcdst
    cudaEventRecord(ev_fork, 0);
    cudaStreamWaitEvent(s_side, ev_fork, 0);
    scan1<<<NB, 512, 0, s_side>>>(ecnt, eoff, bsum);
    scan2<<<1, 128, 0, s_side>>>(bsum, NB);
    scan3<<<NB, 512, 0, s_side>>>(eoff, bsum, cursor);
    scatter_kernel<<<(EE + 255) / 256, 256, 0, s_side>>>(src, dst, cursor, esrc);
    cudaEventRecord(ev_join, s_side);

    gemm_srcdst<<<dim3(GXM, 2), 256, SM_GEMM>>>(h_f16, Ws, bsrc, Wd, bdst, fs, fd);

    cudaStreamWaitEvent(0, ev_join, 0);

    edge_agg_ln<<<(NN + 7) / 8, 256>>>(fs, fd, eoff, ecnt, esrc, attn,
                                       h, g1, be1, h1_f16);

    gemm_ffn1<<<dim3(GXM, 2), 256, SM_GEMM>>>(h1_f16, W1h, bf1, t_f16);
    gemm_ffn2_ln<<<dim3(GXM, 1), 256, SM_GEMM>>>(t_f16, W2h, bf2, h1_f16, g2, be2, out);
}